// round 16
// baseline (speedup 1.0000x reference)
#include <cuda_runtime.h>
#include <cstdint>

// ConstituencyMFVI: B=8, N=192, 3 iterations.
// R16 = R15 VERBATIM (2 CTAs/SM, 512 thr, CROWS=128 single buffer, 4x32-row
// cp.async.bulk chunks, in-place post-butterfly row finish) with the row
// dots PACKED: fma.rn.f32x2 (FFMA2) does 2 MACs/instr, halving the FFMA
// stream (72 -> 36+unpack per thread-iter, ~20% fewer instructions total).
// Issue was the top co-limiter at 47.2%.

#define NDIM    192
#define CROWS   128
#define THREADS 512
#define NTILES  (8 * NDIM)          // 1536
#define BUF_FLOATS (CROWS * NDIM)   // 24576

static const int SMEM_BYTES = (16 + BUF_FLOATS + 3 * NDIM) * 4;   // 100672

__device__ __forceinline__ unsigned smem_u32(const void* p) {
    return (unsigned)__cvta_generic_to_shared(p);
}
__device__ __forceinline__ float sigmoidf_(float x) {
    return 1.0f / (1.0f + __expf(-x));
}
__device__ __forceinline__ unsigned long long ffma2_(unsigned long long v,
                                                     unsigned long long s,
                                                     unsigned long long a) {
    unsigned long long r;
    asm("fma.rn.f32x2 %0, %1, %2, %3;" : "=l"(r) : "l"(v), "l"(s), "l"(a));
    return r;
}
__device__ __forceinline__ float unpack_add_(unsigned long long a) {
    return __uint_as_float((unsigned)a) + __uint_as_float((unsigned)(a >> 32));
}
__device__ __forceinline__ void mbar_wait(unsigned addr, int phase) {
    asm volatile(
        "{\n\t.reg .pred P;\n\t"
        "W_%=:\n\t"
        "mbarrier.try_wait.parity.acquire.cta.shared::cta.b64 P, [%0], %1, 0x989680;\n\t"
        "@P bra.uni D_%=;\n\t"
        "bra.uni W_%=;\n\t"
        "D_%=:\n\t}"
        :: "r"(addr), "r"((unsigned)phase) : "memory");
}

// Issue 4 bulk-copy chunks (32 rows each) for tile g (tid 0 only).
__device__ __forceinline__ void issue_tile(const float* __restrict__ s_pair,
                                           int g, float* buf, unsigned mbar0)
{
    asm volatile("fence.proxy.async.shared::cta;" ::: "memory");
    const bool valid = (g < NTILES);
    const int  i = valid ? (g % NDIM) : 0;
    const int  nRows = NDIM - 1 - i;
    const float* src0 = s_pair + (size_t)g * (NDIM * NDIM)
                      + (size_t)(i + 1) * NDIM;
    #pragma unroll
    for (int c = 0; c < 4; ++c) {
        int nr = nRows - c * 32;
        if (nr > 32) nr = 32;
        unsigned bytes = (valid && nr > 0) ? (unsigned)(nr * NDIM * 4) : 0u;
        unsigned mb = mbar0 + 8 * c;
        asm volatile("mbarrier.arrive.expect_tx.shared.b64 _, [%0], %1;"
                     :: "r"(mb), "r"(bytes) : "memory");
        if (bytes) {
            unsigned dst = smem_u32(buf + c * (32 * NDIM));
            asm volatile(
                "cp.async.bulk.shared::cta.global.mbarrier::complete_tx::bytes "
                "[%0], [%1], %2, [%3];"
                :: "r"(dst), "l"(src0 + c * (32 * NDIM)), "r"(bytes), "r"(mb)
                : "memory");
        }
    }
}

__global__ void __launch_bounds__(THREADS, 2)
mfvi_kernel(const float* __restrict__ s_span,
            const float* __restrict__ s_pair,
            float* __restrict__ out)
{
    extern __shared__ float smem[];
    uint64_t* mbar = reinterpret_cast<uint64_t*>(smem);   // [4]
    float* buf     = smem + 16;                           // [128][192]
    float* sigA    = buf + BUF_FLOATS;                    // [192]
    float* sigB    = sigA + NDIM;                         // [192]
    float* spanS   = sigB + NDIM;                         // [192]

    const int tid = threadIdx.x;
    const int hw  = tid >> 4;        // half-warp 0..31
    const int ll  = tid & 15;
    const int stride = gridDim.x;
    const unsigned mb0 = smem_u32(&mbar[0]);

    // Row owned by this lane (valid for ll < 6):
    const int myr = (ll < 4) ? (hw + 32 * ll) : (CROWS + 32 * (ll - 4) + hw);

    if (tid == 0) {
        #pragma unroll
        for (int s = 0; s < 4; ++s)
            asm volatile("mbarrier.init.shared.b64 [%0], 1;"
                         :: "r"(smem_u32(&mbar[s])) : "memory");
        asm volatile("fence.proxy.async.shared::cta;" ::: "memory");
    }
    __syncthreads();

    if (tid == 0)
        issue_tile(s_pair, blockIdx.x, buf, mb0);

    int n = 0;
    for (int g = blockIdx.x; g < NTILES; g += stride, ++n) {
        const int ph = n & 1;
        const int i        = g % NDIM;
        const int rowStart = i + 1;
        const int nRows    = NDIM - rowStart;
        const float* gbase = s_pair + (size_t)g * (NDIM * NDIM);

        // ---- Setup: sig0 = sigmoid(span); stash span; j<=i outputs ----
        if (tid < NDIM) {
            float sp = s_span[(size_t)g * NDIM + tid];
            float s0v = sigmoidf_(sp);
            sigA[tid] = s0v;
            sigB[tid] = s0v;
            spanS[tid] = sp;
            if (tid <= i) out[(size_t)g * NDIM + tid] = s0v;
        }
        __syncthreads();

        const float s0i  = sigA[i];
        const bool  mine = (ll < 6) && (myr < nRows);
        const int   myj  = rowStart + myr;
        float span_row = 0.0f, sprev = 0.0f, vi = 0.0f, vjj = 0.0f;
        if (mine) {
            span_row = spanS[myj];
            sprev    = sigA[myj];
        }

        #pragma unroll
        for (int it = 0; it < 3; ++it) {
            const float* sg = (it == 1) ? sigB : sigA;
            const ulonglong2* sg2 = reinterpret_cast<const ulonglong2*>(sg);
            const ulonglong2 sp0 = sg2[ll], sp1 = sg2[ll + 16],
                             sp2 = sg2[ll + 32];

            unsigned long long acc[6] = {0ull,0ull,0ull,0ull,0ull,0ull};

            // Overflow rows (128+hw, 160+hw) from gmem/L2 first.
            #pragma unroll
            for (int ov = 0; ov < 2; ++ov) {
                const int r = CROWS + 32 * ov + hw;
                if (r < nRows) {
                    const ulonglong2* rp = reinterpret_cast<const ulonglong2*>(
                        gbase + (size_t)(rowStart + r) * NDIM);
                    ulonglong2 A = rp[ll], B = rp[ll + 16], E = rp[ll + 32];
                    unsigned long long a = 0ull;
                    a = ffma2_(A.x, sp0.x, a); a = ffma2_(A.y, sp0.y, a);
                    a = ffma2_(B.x, sp1.x, a); a = ffma2_(B.y, sp1.y, a);
                    a = ffma2_(E.x, sp2.x, a); a = ffma2_(E.y, sp2.y, a);
                    acc[4 + ov] = a;
                }
            }
            // SMEM chunks: chunk c holds rows 32c..32c+31 (t == c).
            #pragma unroll
            for (int c = 0; c < 4; ++c) {
                if (it == 0) mbar_wait(mb0 + 8 * c, ph);
                const int r = hw + 32 * c;
                if (r < nRows) {
                    const ulonglong2* rp = reinterpret_cast<const ulonglong2*>(
                        buf + (size_t)r * NDIM);
                    ulonglong2 A = rp[ll], B = rp[ll + 16], E = rp[ll + 32];
                    unsigned long long a = 0ull;
                    a = ffma2_(A.x, sp0.x, a); a = ffma2_(A.y, sp0.y, a);
                    a = ffma2_(B.x, sp1.x, a); a = ffma2_(B.y, sp1.y, a);
                    a = ffma2_(E.x, sp2.x, a); a = ffma2_(E.y, sp2.y, a);
                    acc[c] = a;
                }
            }
            // Unpack to scalars, then butterfly (all lanes get all 6 sums).
            float d[6];
            #pragma unroll
            for (int t = 0; t < 6; ++t) d[t] = unpack_add_(acc[t]);
            #pragma unroll
            for (int off = 8; off >= 1; off >>= 1)
                #pragma unroll
                for (int t = 0; t < 6; ++t)
                    d[t] += __shfl_xor_sync(0xffffffffu, d[t], off);

            if (it == 0 && mine) {          // mask scalars (tile resident)
                if (myr < CROWS) {
                    vi  = buf[(size_t)myr * NDIM + i];
                    vjj = buf[(size_t)myr * NDIM + myj];
                } else {
                    vi  = __ldg(gbase + (size_t)myj * NDIM + i);
                    vjj = __ldg(gbase + (size_t)myj * NDIM + myj);
                }
            }
            if (mine) {
                float dsel = d[0];
                if (ll == 1) dsel = d[1];
                if (ll == 2) dsel = d[2];
                if (ll == 3) dsel = d[3];
                if (ll == 4) dsel = d[4];
                if (ll == 5) dsel = d[5];
                float q = span_row + dsel - s0i * vi - sprev * vjj;
                sprev = sigmoidf_(q);
                if (it == 0)      sigB[myj] = sprev;
                else if (it == 1) sigA[myj] = sprev;
                else              out[(size_t)g * NDIM + myj] = sprev;
            }
            __syncthreads();
        }

        // All buffer reads done: issue next tile's TMA.
        if (tid == 0)
            issue_tile(s_pair, g + stride, buf, mb0);
    }
}

extern "C" void kernel_launch(void* const* d_in, const int* in_sizes, int n_in,
                              void* d_out, int out_size)
{
    (void)in_sizes; (void)n_in; (void)out_size;
    const float* s_span = (const float*)d_in[0];
    const float* s_pair = (const float*)d_in[1];
    // d_in[2] = mask: analytic (strict upper triangle), not needed.
    float* out = (float*)d_out;

    int nsm = 148;
    cudaDeviceGetAttribute(&nsm, cudaDevAttrMultiProcessorCount, 0);
    if (nsm <= 0) nsm = 148;
    int grid = 2 * nsm;                 // 2 persistent CTAs per SM
    if (grid > NTILES) grid = NTILES;

    cudaFuncSetAttribute(mfvi_kernel,
                         cudaFuncAttributeMaxDynamicSharedMemorySize, SMEM_BYTES);

    mfvi_kernel<<<grid, THREADS, SMEM_BYTES>>>(s_span, s_pair, out);
}